// round 12
// baseline (speedup 1.0000x reference)
#include <cuda_runtime.h>

// GaussianBlur2D: depthwise 11x11 Gaussian blur, reflect padding.
// x: (16, 64, 512, 512) fp32, sigma: (1,) fp32.
//
// Circular register window (compile-time rotation) + single barrier:
//   - 14-row float4 register window; template OFF rotation => no slide MOVs
//   - refilled slots are the DEAD ones: (OFF+rr)%14  [bug in prev round:
//     wrote (OFF+10+rr)%14, clobbering live rows]
//   - LDGs land directly into freed window slots after the vertical pass
//   - double-buffered smem vblur rows => ONE __syncthreads() per 4 rows
//   - sigma==1.5 fast path with fma.rn.f32 immediate weights; generic
//     runtime-sigma path otherwise
// g2d[i][j] = (h[i]/S)*(h[j]/S) with S = sum(h)  == reference's 2D kernel.

#define KS    11
#define IMG   512
#define NT    128      // threads per block; NT*4 == IMG
#define RPT   4        // output rows per iteration
#define STRIP 128      // output rows per block
#define SVW   528      // smem row: [0..4] halo, [5..516] data, [517..521] halo

// fma.rn.f32 acc = v * <imm> + acc   (imm as PTX hex float literal)
#define FMA_IMM(acc, v, HEX) \
    asm("fma.rn.f32 %0, %1, " HEX ", %0;" : "+f"(acc) : "f"(v))

// Normalized 1D Gaussian weights for sigma=1.5 (IEEE-754 fp32 hex)
#define W_0  "0f3A86CAB4"
#define W_1  "0f3BF8FF33"
#define W_2  "0f3D137578"
#define W_3  "0f3DDFF8A9"
#define W_4  "0f3E5A1E3F"
#define W_5  "0f3E8832BD"
#define W_6  W_4
#define W_7  W_3
#define W_8  W_2
#define W_9  W_1
#define W_10 W_0

// vertical tap i (circular index, compile-time)
#define VT(i, HEX) { const float4 v_ = win[(OFF + r + (i)) % 14];   \
    FMA_IMM(a[0], v_.x, HEX); FMA_IMM(a[1], v_.y, HEX);             \
    FMA_IMM(a[2], v_.z, HEX); FMA_IMM(a[3], v_.w, HEX); }

// horizontal tap j
#define HT(j, HEX) {                                                \
    FMA_IMM(o0, v[(j)],     HEX); FMA_IMM(o1, v[(j) + 1], HEX);     \
    FMA_IMM(o2, v[(j) + 2], HEX); FMA_IMM(o3, v[(j) + 3], HEX); }

__device__ __forceinline__ int refl(int i) {
    i = (i < 0) ? -i : i;
    return (i >= IMG) ? (2 * IMG - 2 - i) : i;
}

// One 4-row iteration. Window invariant on entry:
//   win[(OFF + k) % 14] = input row (y - 5 + k), k = 0..13.
// Vertical pass consumes k = 0..13; slots k = 0..3 (rows y-5..y-2) then die.
// We refill those slots -- win[(OFF + rr) % 14], rr = 0..3 -- with rows
// y+9..y+12, which at OFF' = OFF+4 sit at k' = 10..13: invariant restored.
template<int OFF, bool SPEC>
__device__ __forceinline__ void iter4(const float* __restrict__ img,
                                      float* __restrict__ oimg,
                                      float4 (&win)[14],
                                      float (*s_v)[SVW],
                                      const float* __restrict__ w,
                                      int x, bool edge, int y) {
    // ---- vertical 11-tap (registers only) + STS ----
    #pragma unroll
    for (int r = 0; r < RPT; r++) {
        float a[4] = {0.f, 0.f, 0.f, 0.f};
        if constexpr (SPEC) {
            VT(0, W_0)  VT(1, W_1)  VT(2, W_2)  VT(3, W_3)
            VT(4, W_4)  VT(5, W_5)  VT(6, W_6)  VT(7, W_7)
            VT(8, W_8)  VT(9, W_9)  VT(10, W_10)
        } else {
            #pragma unroll
            for (int i = 0; i < KS; i++) {
                const float  wi = w[i];
                const float4 v  = win[(OFF + r + i) % 14];
                a[0] = fmaf(wi, v.x, a[0]);
                a[1] = fmaf(wi, v.y, a[1]);
                a[2] = fmaf(wi, v.z, a[2]);
                a[3] = fmaf(wi, v.w, a[3]);
            }
        }
        float* sv = s_v[r];
        #pragma unroll
        for (int c = 0; c < 4; c++)            // scalar STS (offset 5+x unaligned)
            sv[5 + x + c] = a[c];

        if (edge) {   // mirrored halo: col -c <- col c ; col 512+k <- col 510-k
            #pragma unroll
            for (int c = 0; c < 4; c++) {
                const int xc = x + c;
                if (xc >= 1   && xc <= 5)   sv[5 - xc]    = a[c];
                if (xc >= 506 && xc <= 510) sv[1027 - xc] = a[c];
            }
        }
    }

    // ---- refill the DEAD slots (k=0..3) with rows y+9..y+12 ----
    #pragma unroll
    for (int rr = 0; rr < RPT; rr++)
        win[(OFF + rr) % 14] =
            *(const float4*)(img + (size_t)refl(y + 9 + rr) * IMG + x);

    __syncthreads();   // single barrier: STS(buf) visible before LDS(buf)

    // ---- horizontal 11-tap: 4 aligned LDS.128 -> 4 outputs per row ----
    #pragma unroll
    for (int r = 0; r < RPT; r++) {
        const float4* vp = (const float4*)&s_v[r][x];   // x mult of 4 -> aligned
        const float4 A = vp[0], B = vp[1], C = vp[2], D = vp[3];
        const float v[16] = {A.x, A.y, A.z, A.w,
                             B.x, B.y, B.z, B.w,
                             C.x, C.y, C.z, C.w,
                             D.x, D.y, D.z, D.w};
        float o0 = 0.f, o1 = 0.f, o2 = 0.f, o3 = 0.f;
        if constexpr (SPEC) {
            HT(0, W_0)  HT(1, W_1)  HT(2, W_2)  HT(3, W_3)
            HT(4, W_4)  HT(5, W_5)  HT(6, W_6)  HT(7, W_7)
            HT(8, W_8)  HT(9, W_9)  HT(10, W_10)
        } else {
            #pragma unroll
            for (int j = 0; j < KS; j++) {
                const float wj = w[j];
                o0 = fmaf(wj, v[j],     o0);
                o1 = fmaf(wj, v[j + 1], o1);
                o2 = fmaf(wj, v[j + 2], o2);
                o3 = fmaf(wj, v[j + 3], o3);
            }
        }
        *(float4*)(oimg + (size_t)(y + r) * IMG + x) = make_float4(o0, o1, o2, o3);
    }
}

template<bool SPEC>
__device__ __forceinline__ void blur_body(const float* __restrict__ img,
                                          float* __restrict__ oimg,
                                          int t, int y0, float sig,
                                          float (*s_v2)[RPT][SVW]) {
    const int x = t << 2;                  // this thread owns columns x..x+3
    const bool edge = (t < 2) || (t >= 126);

    float w[KS];
    if constexpr (!SPEC) {
        float s = fabsf(sig) + 1e-6f;
        float inv = 1.0f / (2.0f * s * s);
        float sum = 0.0f;
        #pragma unroll
        for (int j = 0; j < KS; j++) {
            float r = (float)j - (float)(KS - 1) * 0.5f;
            w[j] = __expf(-r * r * inv);
            sum += w[j];
        }
        float rs = 1.0f / sum;
        #pragma unroll
        for (int j = 0; j < KS; j++) w[j] *= rs;
    }

    // window fill: win[k] = raw input row (y0 + k - 5), k = 0..13
    float4 win[14];
    #pragma unroll
    for (int k = 0; k < 14; k++)
        win[k] = *(const float4*)(img + (size_t)refl(y0 + k - 5) * IMG + x);

    int y = y0;
    int buf = 0;

    // 28 iterations: 4 outer passes x 7 rotations (4*7 == 0 mod 14)
    #pragma unroll 1
    for (int g = 0; g < 4; g++) {
        iter4<0,  SPEC>(img, oimg, win, s_v2[buf], w, x, edge, y); y += 4; buf ^= 1;
        iter4<4,  SPEC>(img, oimg, win, s_v2[buf], w, x, edge, y); y += 4; buf ^= 1;
        iter4<8,  SPEC>(img, oimg, win, s_v2[buf], w, x, edge, y); y += 4; buf ^= 1;
        iter4<12, SPEC>(img, oimg, win, s_v2[buf], w, x, edge, y); y += 4; buf ^= 1;
        iter4<2,  SPEC>(img, oimg, win, s_v2[buf], w, x, edge, y); y += 4; buf ^= 1;
        iter4<6,  SPEC>(img, oimg, win, s_v2[buf], w, x, edge, y); y += 4; buf ^= 1;
        iter4<10, SPEC>(img, oimg, win, s_v2[buf], w, x, edge, y); y += 4; buf ^= 1;
    }
    // tail: 4 iterations (rotation restarts at 0 since 28 ≡ 0 mod 14)
    iter4<0,  SPEC>(img, oimg, win, s_v2[buf], w, x, edge, y); y += 4; buf ^= 1;
    iter4<4,  SPEC>(img, oimg, win, s_v2[buf], w, x, edge, y); y += 4; buf ^= 1;
    iter4<8,  SPEC>(img, oimg, win, s_v2[buf], w, x, edge, y); y += 4; buf ^= 1;
    iter4<12, SPEC>(img, oimg, win, s_v2[buf], w, x, edge, y);
}

__global__ __launch_bounds__(NT, 5)
void gaussian_blur_kernel(const float* __restrict__ in, float* __restrict__ out,
                          const float* __restrict__ sigma) {
    __shared__ __align__(16) float s_v[2][RPT][SVW];

    const int t = threadIdx.x;
    const int plane = blockIdx.x >> 2;
    const int y0 = (blockIdx.x & 3) * STRIP;
    const float* __restrict__ img  = in  + (size_t)plane * (IMG * IMG);
    float*       __restrict__ oimg = out + (size_t)plane * (IMG * IMG);

    const float sig = sigma[0];
    if (fabsf(fabsf(sig) - 1.5f) < 1e-4f) {
        blur_body<true >(img, oimg, t, y0, sig, s_v);
    } else {
        blur_body<false>(img, oimg, t, y0, sig, s_v);
    }
}

extern "C" void kernel_launch(void* const* d_in, const int* in_sizes, int n_in,
                              void* d_out, int out_size) {
    const float* x     = (const float*)d_in[0];
    const float* sigma = (const float*)d_in[1];
    float*       out   = (float*)d_out;

    const int n_img = in_sizes[0] / (IMG * IMG);   // B*C planes

    const int strips = IMG / STRIP;                // 4
    gaussian_blur_kernel<<<n_img * strips, NT>>>(x, out, sigma);
}